// round 9
// baseline (speedup 1.0000x reference)
#include <cuda_runtime.h>
#include <cuda_bf16.h>
#include <math.h>
#include <stdint.h>

#define T_TOK 2048
#define H_DIM 1024
#define F_DIM 4096
#define N_EXP 8
#define NSLOT (T_TOK * 2)

#define AST 24              // smem row stride in bf16 elems (16 + 8 pad) = 48B
#define GU_STAGE 24576      // A hi/lo 12288 + 4 B mats * 3072
#define GU_SMEM  (3 * GU_STAGE)
#define DN_STAGE 24576      // A hi/lo 12288 + 2 B mats * 6144
#define DN_SMEM  (3 * DN_STAGE)

// ---------------- scratch ----------------------------------------------------
__device__ int      g_count[N_EXP];
__device__ int      g_offset[N_EXP];
__device__ int      g_tok_e[NSLOT];
__device__ float    g_tok_w[NSLOT];
__device__ int      g_tok_rank[NSLOT];
__device__ int      g_slot_token[NSLOT];
__device__ int      g_slot_of[NSLOT];
__device__ uint16_t g_xh[(size_t)T_TOK * H_DIM];
__device__ uint16_t g_xl[(size_t)T_TOK * H_DIM];
// transposed + split weights: gate/up [E][F][H], down [E][H][F]
__device__ uint16_t g_bgh[(size_t)N_EXP * H_DIM * F_DIM];
__device__ uint16_t g_bgl[(size_t)N_EXP * H_DIM * F_DIM];
__device__ uint16_t g_buh[(size_t)N_EXP * H_DIM * F_DIM];
__device__ uint16_t g_bul[(size_t)N_EXP * H_DIM * F_DIM];
__device__ uint16_t g_bdh[(size_t)N_EXP * F_DIM * H_DIM];
__device__ uint16_t g_bdl[(size_t)N_EXP * F_DIM * H_DIM];
__device__ uint16_t g_acth[(size_t)NSLOT * F_DIM];
__device__ uint16_t g_actl[(size_t)NSLOT * F_DIM];
__device__ float    g_part[(size_t)NSLOT * H_DIM];

// ---------------- helpers ----------------------------------------------------
__device__ __forceinline__ uint32_t smem_u32(const void* p) {
    return (uint32_t)__cvta_generic_to_shared(p);
}
__device__ __forceinline__ void cpa16(void* dst, const void* src) {
    asm volatile("cp.async.cg.shared.global [%0], [%1], 16;"
                 :: "r"(smem_u32(dst)), "l"(src));
}
__device__ __forceinline__ void cp_commit() { asm volatile("cp.async.commit_group;"); }
__device__ __forceinline__ void cp_wait1()  { asm volatile("cp.async.wait_group 1;"); }
__device__ __forceinline__ void cp_wait0()  { asm volatile("cp.async.wait_group 0;"); }

__device__ __forceinline__ void ldsm_x4(uint32_t* r, uint32_t addr) {
    asm volatile("ldmatrix.sync.aligned.m8n8.x4.shared.b16 {%0,%1,%2,%3},[%4];"
                 : "=r"(r[0]), "=r"(r[1]), "=r"(r[2]), "=r"(r[3]) : "r"(addr));
}
__device__ __forceinline__ void mma_bf16(float* c, const uint32_t* a, const uint32_t* b) {
    asm volatile(
        "mma.sync.aligned.m16n8k16.row.col.f32.bf16.bf16.f32 "
        "{%0,%1,%2,%3},{%4,%5,%6,%7},{%8,%9},{%0,%1,%2,%3};"
        : "+f"(c[0]), "+f"(c[1]), "+f"(c[2]), "+f"(c[3])
        : "r"(a[0]), "r"(a[1]), "r"(a[2]), "r"(a[3]), "r"(b[0]), "r"(b[1]));
}
__device__ __forceinline__ void split2(float v0, float v1, uint32_t& h, uint32_t& l) {
    __nv_bfloat16 h0 = __float2bfloat16_rn(v0);
    __nv_bfloat16 h1 = __float2bfloat16_rn(v1);
    __nv_bfloat16 l0 = __float2bfloat16_rn(v0 - __bfloat162float(h0));
    __nv_bfloat16 l1 = __float2bfloat16_rn(v1 - __bfloat162float(h1));
    h = (uint32_t)*(uint16_t*)&h0 | ((uint32_t)*(uint16_t*)&h1 << 16);
    l = (uint32_t)*(uint16_t*)&l0 | ((uint32_t)*(uint16_t*)&l1 << 16);
}

// ---------------- routing ----------------------------------------------------
__global__ void zero_counts_kernel() {
    if (threadIdx.x < N_EXP) g_count[threadIdx.x] = 0;
}

__global__ void router_kernel(const float* __restrict__ x,
                              const float* __restrict__ gw) {
    int gwarp = (blockIdx.x * blockDim.x + threadIdx.x) >> 5;
    int lane  = threadIdx.x & 31;
    if (gwarp >= T_TOK) return;
    const float* xr = x + (size_t)gwarp * H_DIM;
    float acc[N_EXP];
#pragma unroll
    for (int e = 0; e < N_EXP; e++) acc[e] = 0.f;
    for (int h = lane; h < H_DIM; h += 32) {
        float xv = xr[h];
        const float* g = gw + h * N_EXP;
#pragma unroll
        for (int e = 0; e < N_EXP; e++) acc[e] += xv * g[e];
    }
#pragma unroll
    for (int e = 0; e < N_EXP; e++) {
#pragma unroll
        for (int off = 16; off > 0; off >>= 1)
            acc[e] += __shfl_xor_sync(0xffffffffu, acc[e], off);
    }
    if (lane == 0) {
        float m = acc[0];
#pragma unroll
        for (int e = 1; e < N_EXP; e++) m = fmaxf(m, acc[e]);
        float p[N_EXP], s = 0.f;
#pragma unroll
        for (int e = 0; e < N_EXP; e++) { p[e] = expf(acc[e] - m); s += p[e]; }
        float inv = 1.f / s;
#pragma unroll
        for (int e = 0; e < N_EXP; e++) p[e] *= inv;
        int i0 = 0;
#pragma unroll
        for (int e = 1; e < N_EXP; e++) if (p[e] > p[i0]) i0 = e;
        int i1 = (i0 == 0) ? 1 : 0;
#pragma unroll
        for (int e = 0; e < N_EXP; e++)
            if (e != i0 && p[e] > p[i1]) i1 = e;
        float eb = expf(p[i1] - p[i0]);
        float w0 = 1.f / (1.f + eb);
        float w1 = eb * w0;
        int r0 = atomicAdd(&g_count[i0], 1);
        int r1 = atomicAdd(&g_count[i1], 1);
        g_tok_e[gwarp * 2 + 0]    = i0;
        g_tok_e[gwarp * 2 + 1]    = i1;
        g_tok_w[gwarp * 2 + 0]    = w0;
        g_tok_w[gwarp * 2 + 1]    = w1;
        g_tok_rank[gwarp * 2 + 0] = r0;
        g_tok_rank[gwarp * 2 + 1] = r1;
    }
}

__global__ void scan_scatter_kernel() {
    __shared__ int soff[N_EXP];
    if (threadIdx.x == 0) {
        int s = 0;
        for (int e = 0; e < N_EXP; e++) { soff[e] = s; g_offset[e] = s; s += g_count[e]; }
    }
    __syncthreads();
    for (int t = threadIdx.x; t < T_TOK; t += blockDim.x) {
#pragma unroll
        for (int k = 0; k < 2; k++) {
            int e = g_tok_e[t * 2 + k];
            int slot = soff[e] + g_tok_rank[t * 2 + k];
            g_slot_token[slot] = t;
            g_slot_of[t * 2 + k] = slot;
        }
    }
}

// ---------------- split x ----------------------------------------------------
__global__ void split_x_kernel(const float* __restrict__ src) {
    int i = blockIdx.x * blockDim.x + threadIdx.x;
    float4 v = ((const float4*)src)[i];
    uint32_t h0, l0, h1, l1;
    split2(v.x, v.y, h0, l0);
    split2(v.z, v.w, h1, l1);
    ((uint2*)g_xh)[i] = make_uint2(h0, h1);
    ((uint2*)g_xl)[i] = make_uint2(l0, l1);
}

// ---------------- split + transpose weights ----------------------------------
// src [E][R][C] fp32 -> dst [E][C][R] bf16 hi/lo, 32x32 tiles
__global__ void __launch_bounds__(256)
split_transpose_kernel(const float* __restrict__ wg,
                       const float* __restrict__ wu,
                       const float* __restrict__ wd) {
    __shared__ float s[32][33];
    int b   = blockIdx.x;
    int mat = b >> 15;
    int rem = b & 32767;
    int e   = rem >> 12;
    int t   = rem & 4095;

    const float* src;
    uint16_t *dh, *dl;
    int C, tr, tc;
    if (mat == 0) { src = wg; dh = g_bgh; dl = g_bgl; C = F_DIM; tr = t >> 7; tc = t & 127; }
    else if (mat == 1) { src = wu; dh = g_buh; dl = g_bul; C = F_DIM; tr = t >> 7; tc = t & 127; }
    else { src = wd; dh = g_bdh; dl = g_bdl; C = H_DIM; tr = t >> 5; tc = t & 31; }
    int R = (F_DIM * H_DIM) / C;
    size_t mbase = (size_t)e * F_DIM * H_DIM;
    int r0 = tr * 32, c0 = tc * 32;

    int rr = threadIdx.x >> 3, cc = (threadIdx.x & 7) * 4;
    float4 v = *(const float4*)(src + mbase + (size_t)(r0 + rr) * C + c0 + cc);
    s[rr][cc + 0] = v.x; s[rr][cc + 1] = v.y; s[rr][cc + 2] = v.z; s[rr][cc + 3] = v.w;
    __syncthreads();

    float w0 = s[cc + 0][rr], w1 = s[cc + 1][rr];
    float w2 = s[cc + 2][rr], w3 = s[cc + 3][rr];
    uint32_t h0, l0, h1, l1;
    split2(w0, w1, h0, l0);
    split2(w2, w3, h1, l1);
    size_t o = mbase + (size_t)(c0 + rr) * R + r0 + cc;
    *(uint2*)(dh + o) = make_uint2(h0, h1);
    *(uint2*)(dl + o) = make_uint2(l0, l1);
}

// ---------------- gateup GEMM: BM=128, BN=64, BK=16, 512 thr, 3-stage --------
// warp tile 16x32: warp_m = wid>>1 (8), warp_n = wid&1 (2)
__global__ void __launch_bounds__(512, 1)
gateup_kernel() {
    extern __shared__ char smem[];
    int e = blockIdx.z;
    int n = g_count[e];
    int rowbase = blockIdx.y * 128;
    if (rowbase >= n) return;
    int off = g_offset[e];
    int f0  = blockIdx.x * 64;

    int tid = threadIdx.x, lane = tid & 31, wid = tid >> 5;
    int warp_m = wid >> 1, warp_n = wid & 1;

    // A loader: 128 rows x 4 chunks (hi0,hi1,lo0,lo1)
    int arow = tid >> 2, q = tid & 3;
    int srow = rowbase + arow; if (srow > n - 1) srow = n - 1;
    size_t xoff = (size_t)g_slot_token[off + srow] * H_DIM + (q & 1) * 8;
    const uint16_t* asrc = ((q >> 1) ? g_xl : g_xh) + xoff;
    uint32_t adst = (q >> 1) * 6144 + (uint32_t)(arow * AST + (q & 1) * 8) * 2;

    // B loader: 4 mats x 64 rows x 2 halves
    int bmat = tid >> 7, brow = (tid >> 1) & 63, bhalf = tid & 1;
    const uint16_t* bbase = (bmat == 0) ? g_bgh : (bmat == 1) ? g_bgl
                          : (bmat == 2) ? g_buh : g_bul;
    const uint16_t* bsrc = bbase + (size_t)e * H_DIM * F_DIM
                         + (size_t)(f0 + brow) * H_DIM + bhalf * 8;
    uint32_t bdst = 12288 + bmat * 3072 + (uint32_t)(brow * AST + bhalf * 8) * 2;

    float accg[4][4], accu[4][4];
#pragma unroll
    for (int j = 0; j < 4; j++)
#pragma unroll
        for (int qq = 0; qq < 4; qq++) { accg[j][qq] = 0.f; accu[j][qq] = 0.f; }

    auto load_tile = [&](int st, int kt) {
        char* base = smem + st * GU_STAGE;
        cpa16(base + adst, asrc + kt * 16);
        cpa16(base + bdst, bsrc + kt * 16);
        cp_commit();
    };

    load_tile(0, 0);
    load_tile(1, 1);
    const int KT = H_DIM / 16;   // 64
    int cs = 0;
#pragma unroll 1
    for (int kt = 0; kt < KT; kt++) {
        if (kt + 1 < KT) cp_wait1(); else cp_wait0();
        __syncthreads();
        if (kt + 2 < KT) {
            int ld = cs + 2; if (ld >= 3) ld -= 3;
            load_tile(ld, kt + 2);
        }

        char* base = smem + cs * GU_STAGE;
        // A frags (m16k16, hi/lo)
        int ar = warp_m * 16 + (lane & 7) + ((lane >> 3) & 1) * 8;
        int ak = ((lane >> 4) & 1) * 8;
        uint32_t ah[4], al[4];
        ldsm_x4(ah, smem_u32(base + (ar * AST + ak) * 2));
        ldsm_x4(al, smem_u32(base + 6144 + (ar * AST + ak) * 2));
        // B frags: non-trans x4 over [n][k] rows: n16 x k16 per ldsm
        int br = (lane & 7) + ((lane >> 4) & 1) * 8;
        int bk = ((lane >> 3) & 1) * 8;
#pragma unroll
        for (int g16 = 0; g16 < 2; g16++) {
            int nn = warp_n * 32 + g16 * 16;
            uint32_t boff = (uint32_t)((nn + br) * AST + bk) * 2;
            uint32_t bgh[4], bgl[4], buh[4], bul[4];
            ldsm_x4(bgh, smem_u32(base + 12288 + 0 * 3072 + boff));
            ldsm_x4(bgl, smem_u32(base + 12288 + 1 * 3072 + boff));
            ldsm_x4(buh, smem_u32(base + 12288 + 2 * 3072 + boff));
            ldsm_x4(bul, smem_u32(base + 12288 + 3 * 3072 + boff));
#pragma unroll
            for (int hh = 0; hh < 2; hh++) {
                int nt = g16 * 2 + hh;
                mma_bf16(accg[nt], ah, bgh + 2 * hh);
                mma_bf16(accg[nt], ah, bgl + 2 * hh);
                mma_bf16(accg[nt], al, bgh + 2 * hh);
                mma_bf16(accu[nt], ah, buh + 2 * hh);
                mma_bf16(accu[nt], ah, bul + 2 * hh);
                mma_bf16(accu[nt], al, buh + 2 * hh);
            }
        }
        cs = cs + 1; if (cs == 3) cs = 0;
    }

    // epilogue: SwiGLU + split-store activations
    int gq = lane >> 2, tq = lane & 3;
#pragma unroll
    for (int nt = 0; nt < 4; nt++) {
        int fc = f0 + warp_n * 32 + nt * 8 + tq * 2;
#pragma unroll
        for (int h2 = 0; h2 < 2; h2++) {
            int row = rowbase + warp_m * 16 + gq + h2 * 8;
            if (row < n) {
                float g0 = accg[nt][h2 * 2],     g1 = accg[nt][h2 * 2 + 1];
                float u0 = accu[nt][h2 * 2],     u1 = accu[nt][h2 * 2 + 1];
                float v0 = g0 / (1.f + expf(-g0)) * u0;
                float v1 = g1 / (1.f + expf(-g1)) * u1;
                uint32_t hh, ll;
                split2(v0, v1, hh, ll);
                size_t basei = (size_t)(off + row) * F_DIM + fc;
                *(uint32_t*)(g_acth + basei) = hh;
                *(uint32_t*)(g_actl + basei) = ll;
            }
        }
    }
}

// ---------------- down GEMM: BM=128, BN=128, BK=16, 512 thr, 3-stage ---------
// warp tile 16x64: warp_m = wid>>1 (8), warp_n = wid&1 (2)
__global__ void __launch_bounds__(512, 1)
down_kernel() {
    extern __shared__ char smem[];
    int e = blockIdx.z;
    int n = g_count[e];
    int rowbase = blockIdx.y * 128;
    if (rowbase >= n) return;
    int off = g_offset[e];
    int h0  = blockIdx.x * 128;

    int tid = threadIdx.x, lane = tid & 31, wid = tid >> 5;
    int warp_m = wid >> 1, warp_n = wid & 1;

    int arow = tid >> 2, q = tid & 3;
    int srow = rowbase + arow; if (srow > n - 1) srow = n - 1;
    size_t aoff = (size_t)(off + srow) * F_DIM + (q & 1) * 8;
    const uint16_t* asrc = ((q >> 1) ? g_actl : g_acth) + aoff;
    uint32_t adst = (q >> 1) * 6144 + (uint32_t)(arow * AST + (q & 1) * 8) * 2;

    // B loader: 2 mats x 128 rows x 2 halves
    int bmat = tid >> 8, brow = (tid >> 1) & 127, bhalf = tid & 1;
    const uint16_t* bbase = bmat ? g_bdl : g_bdh;
    const uint16_t* bsrc = bbase + (size_t)e * H_DIM * F_DIM
                         + (size_t)(h0 + brow) * F_DIM + bhalf * 8;
    uint32_t bdst = 12288 + bmat * 6144 + (uint32_t)(brow * AST + bhalf * 8) * 2;

    float acc[8][4];
#pragma unroll
    for (int j = 0; j < 8; j++)
#pragma unroll
        for (int qq = 0; qq < 4; qq++) acc[j][qq] = 0.f;

    auto load_tile = [&](int st, int kt) {
        char* base = smem + st * DN_STAGE;
        cpa16(base + adst, asrc + kt * 16);
        cpa16(base + bdst, bsrc + kt * 16);
        cp_commit();
    };

    load_tile(0, 0);
    load_tile(1, 1);
    const int KT = F_DIM / 16;   // 256
    int cs = 0;
#pragma unroll 1
    for (int kt = 0; kt < KT; kt++) {
        if (kt + 1 < KT) cp_wait1(); else cp_wait0();
        __syncthreads();
        if (kt + 2 < KT) {
            int ld = cs + 2; if (ld >= 3) ld -= 3;
            load_tile(ld, kt + 2);
        }

        char* base = smem + cs * DN_STAGE;
        int ar = warp_m * 16 + (lane & 7) + ((lane >> 3) & 1) * 8;
        int ak = ((lane >> 4) & 1) * 8;
        uint32_t ah[4], al[4];
        ldsm_x4(ah, smem_u32(base + (ar * AST + ak) * 2));
        ldsm_x4(al, smem_u32(base + 6144 + (ar * AST + ak) * 2));
        int br = (lane & 7) + ((lane >> 4) & 1) * 8;
        int bk = ((lane >> 3) & 1) * 8;
#pragma unroll
        for (int g16 = 0; g16 < 4; g16++) {
            int nn = warp_n * 64 + g16 * 16;
            uint32_t boff = (uint32_t)((nn + br) * AST + bk) * 2;
            uint32_t bh[4], bl[4];
            ldsm_x4(bh, smem_u32(base + 12288 + boff));
            ldsm_x4(bl, smem_u32(base + 12288 + 6144 + boff));
#pragma unroll
            for (int hh = 0; hh < 2; hh++) {
                int nt = g16 * 2 + hh;
                mma_bf16(acc[nt], ah, bh + 2 * hh);
                mma_bf16(acc[nt], ah, bl + 2 * hh);
                mma_bf16(acc[nt], al, bh + 2 * hh);
            }
        }
        cs = cs + 1; if (cs == 3) cs = 0;
    }

    int gq = lane >> 2, tq = lane & 3;
#pragma unroll
    for (int nt = 0; nt < 8; nt++) {
        int hc = h0 + warp_n * 64 + nt * 8 + tq * 2;
#pragma unroll
        for (int h2 = 0; h2 < 2; h2++) {
            int row = rowbase + warp_m * 16 + gq + h2 * 8;
            if (row < n) {
                float2 v = make_float2(acc[nt][h2 * 2], acc[nt][h2 * 2 + 1]);
                *(float2*)(g_part + (size_t)(off + row) * H_DIM + hc) = v;
            }
        }
    }
}

// ---------------- combine ----------------------------------------------------
__global__ void combine_kernel(float* __restrict__ out) {
    int idx = blockIdx.x * blockDim.x + threadIdx.x;
    if (idx >= T_TOK * H_DIM) return;
    int t = idx >> 10;
    int h = idx & 1023;
    int   s0 = g_slot_of[t * 2 + 0];
    int   s1 = g_slot_of[t * 2 + 1];
    float w0 = g_tok_w[t * 2 + 0];
    float w1 = g_tok_w[t * 2 + 1];
    out[idx] = w0 * g_part[(size_t)s0 * H_DIM + h] +
               w1 * g_part[(size_t)s1 * H_DIM + h];
}

// ---------------- launch -----------------------------------------------------
extern "C" void kernel_launch(void* const* d_in, const int* in_sizes, int n_in,
                              void* d_out, int out_size) {
    const float* x      = (const float*)d_in[0];
    const float* gate_w = (const float*)d_in[1];
    const float* w_gate = (const float*)d_in[2];
    const float* w_up   = (const float*)d_in[3];
    const float* w_down = (const float*)d_in[4];
    float* out = (float*)d_out;

    cudaFuncSetAttribute(gateup_kernel, cudaFuncAttributeMaxDynamicSharedMemorySize, GU_SMEM);
    cudaFuncSetAttribute(down_kernel,   cudaFuncAttributeMaxDynamicSharedMemorySize, DN_SMEM);

    zero_counts_kernel<<<1, 32>>>();
    router_kernel<<<T_TOK / 8, 256>>>(x, gate_w);
    scan_scatter_kernel<<<1, 256>>>();
    split_x_kernel<<<(T_TOK * H_DIM / 4) / 256, 256>>>(x);
    split_transpose_kernel<<<3 * 8 * 32 * 128, 256>>>(w_gate, w_up, w_down);
    gateup_kernel<<<dim3(F_DIM / 64, NSLOT / 128, N_EXP), 512, GU_SMEM>>>();
    down_kernel<<<dim3(H_DIM / 128, NSLOT / 128, N_EXP), 512, DN_SMEM>>>();
    combine_kernel<<<(T_TOK * H_DIM) / 256, 256>>>(out);
}

// round 11
// speedup vs baseline: 1.4860x; 1.4860x over previous
#include <cuda_runtime.h>
#include <cuda_bf16.h>
#include <math.h>
#include <stdint.h>

#define T_TOK 2048
#define H_DIM 1024
#define F_DIM 4096
#define N_EXP 8
#define NSLOT (T_TOK * 2)

#define GU_STAGE 16384      // A hi 4096 + A lo 4096 + 4 B mats * 2048
#define GU_SMEM  (3 * GU_STAGE)
#define DN_STAGE 16384      // A hi 4096 + A lo 4096 + 2 B mats * 4096
#define DN_SMEM  (3 * DN_STAGE)

// ---------------- scratch ----------------------------------------------------
__device__ int      g_count[N_EXP];
__device__ int      g_offset[N_EXP];
__device__ int      g_tok_e[NSLOT];
__device__ float    g_tok_w[NSLOT];
__device__ int      g_tok_rank[NSLOT];
__device__ int      g_slot_token[NSLOT];
__device__ int      g_slot_of[NSLOT];
__device__ uint16_t g_xh[(size_t)T_TOK * H_DIM];
__device__ uint16_t g_xl[(size_t)T_TOK * H_DIM];
// transposed + split weights: gate/up [E][F][H], down [E][H][F]
__device__ uint16_t g_bgh[(size_t)N_EXP * H_DIM * F_DIM];
__device__ uint16_t g_bgl[(size_t)N_EXP * H_DIM * F_DIM];
__device__ uint16_t g_buh[(size_t)N_EXP * H_DIM * F_DIM];
__device__ uint16_t g_bul[(size_t)N_EXP * H_DIM * F_DIM];
__device__ uint16_t g_bdh[(size_t)N_EXP * F_DIM * H_DIM];
__device__ uint16_t g_bdl[(size_t)N_EXP * F_DIM * H_DIM];
__device__ uint16_t g_acth[(size_t)NSLOT * F_DIM];
__device__ uint16_t g_actl[(size_t)NSLOT * F_DIM];
__device__ float    g_part[(size_t)NSLOT * H_DIM];

// ---------------- helpers ----------------------------------------------------
__device__ __forceinline__ uint32_t smem_u32(const void* p) {
    return (uint32_t)__cvta_generic_to_shared(p);
}
// pad-free conflict-free layout for 16-elem (32B) rows, two 16B halves
__device__ __forceinline__ uint32_t swz(uint32_t row, uint32_t half) {
    return row * 32 + ((half ^ ((row >> 2) & 1)) << 4);
}
__device__ __forceinline__ void cpa16(void* dst, const void* src) {
    asm volatile("cp.async.cg.shared.global [%0], [%1], 16;"
                 :: "r"(smem_u32(dst)), "l"(src));
}
__device__ __forceinline__ void cp_commit() { asm volatile("cp.async.commit_group;"); }
__device__ __forceinline__ void cp_wait1()  { asm volatile("cp.async.wait_group 1;"); }
__device__ __forceinline__ void cp_wait0()  { asm volatile("cp.async.wait_group 0;"); }

__device__ __forceinline__ void ldsm_x4(uint32_t* r, uint32_t addr) {
    asm volatile("ldmatrix.sync.aligned.m8n8.x4.shared.b16 {%0,%1,%2,%3},[%4];"
                 : "=r"(r[0]), "=r"(r[1]), "=r"(r[2]), "=r"(r[3]) : "r"(addr));
}
__device__ __forceinline__ void mma_bf16(float* c, const uint32_t* a, const uint32_t* b) {
    asm volatile(
        "mma.sync.aligned.m16n8k16.row.col.f32.bf16.bf16.f32 "
        "{%0,%1,%2,%3},{%4,%5,%6,%7},{%8,%9},{%0,%1,%2,%3};"
        : "+f"(c[0]), "+f"(c[1]), "+f"(c[2]), "+f"(c[3])
        : "r"(a[0]), "r"(a[1]), "r"(a[2]), "r"(a[3]), "r"(b[0]), "r"(b[1]));
}
__device__ __forceinline__ void split2(float v0, float v1, uint32_t& h, uint32_t& l) {
    __nv_bfloat16 h0 = __float2bfloat16_rn(v0);
    __nv_bfloat16 h1 = __float2bfloat16_rn(v1);
    __nv_bfloat16 l0 = __float2bfloat16_rn(v0 - __bfloat162float(h0));
    __nv_bfloat16 l1 = __float2bfloat16_rn(v1 - __bfloat162float(h1));
    h = (uint32_t)*(uint16_t*)&h0 | ((uint32_t)*(uint16_t*)&h1 << 16);
    l = (uint32_t)*(uint16_t*)&l0 | ((uint32_t)*(uint16_t*)&l1 << 16);
}

// ---------------- launch 1: split+transpose weights (+ zero counters) --------
// src [E][R][C] fp32 -> dst [E][C][R] bf16 hi/lo, 32x32 tiles
__global__ void __launch_bounds__(256)
split_transpose_zero(const float* __restrict__ wg,
                     const float* __restrict__ wu,
                     const float* __restrict__ wd) {
    if (blockIdx.x == 0 && threadIdx.x < N_EXP) g_count[threadIdx.x] = 0;

    __shared__ float s[32][33];
    int b   = blockIdx.x;
    int mat = b >> 15;
    int rem = b & 32767;
    int e   = rem >> 12;
    int t   = rem & 4095;

    const float* src;
    uint16_t *dh, *dl;
    int C, tr, tc;
    if (mat == 0) { src = wg; dh = g_bgh; dl = g_bgl; C = F_DIM; tr = t >> 7; tc = t & 127; }
    else if (mat == 1) { src = wu; dh = g_buh; dl = g_bul; C = F_DIM; tr = t >> 7; tc = t & 127; }
    else { src = wd; dh = g_bdh; dl = g_bdl; C = H_DIM; tr = t >> 5; tc = t & 31; }
    int R = (F_DIM * H_DIM) / C;
    size_t mbase = (size_t)e * F_DIM * H_DIM;
    int r0 = tr * 32, c0 = tc * 32;

    int rr = threadIdx.x >> 3, cc = (threadIdx.x & 7) * 4;
    float4 v = *(const float4*)(src + mbase + (size_t)(r0 + rr) * C + c0 + cc);
    s[rr][cc + 0] = v.x; s[rr][cc + 1] = v.y; s[rr][cc + 2] = v.z; s[rr][cc + 3] = v.w;
    __syncthreads();

    float w0 = s[cc + 0][rr], w1 = s[cc + 1][rr];
    float w2 = s[cc + 2][rr], w3 = s[cc + 3][rr];
    uint32_t h0, l0, h1, l1;
    split2(w0, w1, h0, l0);
    split2(w2, w3, h1, l1);
    size_t o = mbase + (size_t)(c0 + rr) * R + r0 + cc;
    *(uint2*)(dh + o) = make_uint2(h0, h1);
    *(uint2*)(dl + o) = make_uint2(l0, l1);
}

// ---------------- launch 2: router (warp/token) + split x --------------------
__global__ void router_splitx(const float* __restrict__ x,
                              const float* __restrict__ gw) {
    int gwarp = (blockIdx.x * blockDim.x + threadIdx.x) >> 5;
    int lane  = threadIdx.x & 31;
    const float* xr = x + (size_t)gwarp * H_DIM;
    float acc[N_EXP];
#pragma unroll
    for (int e = 0; e < N_EXP; e++) acc[e] = 0.f;
    for (int h = lane; h < H_DIM; h += 32) {
        float xv = xr[h];
        const float* g = gw + h * N_EXP;
#pragma unroll
        for (int e = 0; e < N_EXP; e++) acc[e] += xv * g[e];
    }
#pragma unroll
    for (int e = 0; e < N_EXP; e++) {
#pragma unroll
        for (int off = 16; off > 0; off >>= 1)
            acc[e] += __shfl_xor_sync(0xffffffffu, acc[e], off);
    }
    if (lane == 0) {
        float m = acc[0];
#pragma unroll
        for (int e = 1; e < N_EXP; e++) m = fmaxf(m, acc[e]);
        float p[N_EXP], s = 0.f;
#pragma unroll
        for (int e = 0; e < N_EXP; e++) { p[e] = expf(acc[e] - m); s += p[e]; }
        float inv = 1.f / s;
#pragma unroll
        for (int e = 0; e < N_EXP; e++) p[e] *= inv;
        int i0 = 0;
#pragma unroll
        for (int e = 1; e < N_EXP; e++) if (p[e] > p[i0]) i0 = e;
        int i1 = (i0 == 0) ? 1 : 0;
#pragma unroll
        for (int e = 0; e < N_EXP; e++)
            if (e != i0 && p[e] > p[i1]) i1 = e;
        float eb = expf(p[i1] - p[i0]);
        float w0 = 1.f / (1.f + eb);
        float w1 = eb * w0;
        int r0 = atomicAdd(&g_count[i0], 1);
        int r1 = atomicAdd(&g_count[i1], 1);
        g_tok_e[gwarp * 2 + 0]    = i0;
        g_tok_e[gwarp * 2 + 1]    = i1;
        g_tok_w[gwarp * 2 + 0]    = w0;
        g_tok_w[gwarp * 2 + 1]    = w1;
        g_tok_rank[gwarp * 2 + 0] = r0;
        g_tok_rank[gwarp * 2 + 1] = r1;
    }
    // grid-stride split of x into bf16 hi/lo (65536 threads, 524288 float4)
    int tidg = blockIdx.x * blockDim.x + threadIdx.x;
    for (int i = tidg; i < T_TOK * H_DIM / 4; i += 65536) {
        float4 v = ((const float4*)x)[i];
        uint32_t h0, l0, h1, l1;
        split2(v.x, v.y, h0, l0);
        split2(v.z, v.w, h1, l1);
        ((uint2*)g_xh)[i] = make_uint2(h0, h1);
        ((uint2*)g_xl)[i] = make_uint2(l0, l1);
    }
}

// ---------------- launch 3: prefix offsets + scatter --------------------------
__global__ void scan_scatter_kernel() {
    __shared__ int soff[N_EXP];
    if (threadIdx.x == 0) {
        int s = 0;
        for (int e = 0; e < N_EXP; e++) { soff[e] = s; g_offset[e] = s; s += g_count[e]; }
    }
    __syncthreads();
    for (int t = threadIdx.x; t < T_TOK; t += blockDim.x) {
#pragma unroll
        for (int k = 0; k < 2; k++) {
            int e = g_tok_e[t * 2 + k];
            int slot = soff[e] + g_tok_rank[t * 2 + k];
            g_slot_token[slot] = t;
            g_slot_of[t * 2 + k] = slot;
        }
    }
}

// ---------------- launch 4: gateup GEMM (PROFILED) ----------------------------
// BM=128, BN=64, BK=16, 256 thr, warps 4x2 (32x32 tiles), 3-stage, 2 CTA/SM
__global__ void __launch_bounds__(256, 2)
gateup_kernel() {
    extern __shared__ char smem[];
    int e = blockIdx.z;
    int n = g_count[e];
    int rowbase = blockIdx.y * 128;
    if (rowbase >= n) return;
    int off = g_offset[e];
    int f0  = blockIdx.x * 64;

    int tid = threadIdx.x, lane = tid & 31, wid = tid >> 5;
    int warp_m = wid >> 1, warp_n = wid & 1;

    // A loader: row = tid>>1 (0..127), half = tid&1; hi + lo = 2 cpa16
    int arow = tid >> 1, ahalf = tid & 1;
    int srow = rowbase + arow; if (srow > n - 1) srow = n - 1;
    size_t xoff = (size_t)g_slot_token[off + srow] * H_DIM + ahalf * 8;
    const uint16_t* asrc_h = g_xh + xoff;
    const uint16_t* asrc_l = g_xl + xoff;
    uint32_t adst = swz(arow, ahalf);

    // B loader: 4 mats x 64 rows x 2 halves = 512 -> 2 cpa16/thread
    const uint16_t* bsrc[2];
    uint32_t bdst[2];
#pragma unroll
    for (int c = 0; c < 2; c++) {
        int idx = tid + c * 256;
        int mat = idx >> 7, rem = idx & 127;
        int brow = rem >> 1, bh = rem & 1;
        const uint16_t* base = (mat == 0) ? g_bgh : (mat == 1) ? g_bgl
                             : (mat == 2) ? g_buh : g_bul;
        bsrc[c] = base + (size_t)e * H_DIM * F_DIM + (size_t)(f0 + brow) * H_DIM + bh * 8;
        bdst[c] = 8192 + mat * 2048 + swz(brow, bh);
    }

    float accg[2][4][4], accu[2][4][4];
#pragma unroll
    for (int i = 0; i < 2; i++)
#pragma unroll
        for (int j = 0; j < 4; j++)
#pragma unroll
            for (int q = 0; q < 4; q++) { accg[i][j][q] = 0.f; accu[i][j][q] = 0.f; }

    auto load_tile = [&](int st, int kt) {
        char* base = smem + st * GU_STAGE;
        cpa16(base + adst,        asrc_h + kt * 16);
        cpa16(base + 4096 + adst, asrc_l + kt * 16);
        cpa16(base + bdst[0], bsrc[0] + kt * 16);
        cpa16(base + bdst[1], bsrc[1] + kt * 16);
        cp_commit();
    };

    load_tile(0, 0);
    load_tile(1, 1);
    const int KT = H_DIM / 16;   // 64
    int cs = 0;
#pragma unroll 1
    for (int kt = 0; kt < KT; kt++) {
        if (kt + 1 < KT) cp_wait1(); else cp_wait0();
        __syncthreads();
        if (kt + 2 < KT) {
            int ld = cs + 2; if (ld >= 3) ld -= 3;
            load_tile(ld, kt + 2);
        }

        char* base = smem + cs * GU_STAGE;
        // A fragments: m16k16 hi/lo for 2 m-tiles
        uint32_t ah[2][4], al[2][4];
        {
            int r8 = (lane & 7) + ((lane >> 3) & 1) * 8;
            uint32_t kh = (lane >> 4) & 1;
#pragma unroll
            for (int mt = 0; mt < 2; mt++) {
                uint32_t ao = swz((uint32_t)(warp_m * 32 + mt * 16 + r8), kh);
                ldsm_x4(ah[mt], smem_u32(base + ao));
                ldsm_x4(al[mt], smem_u32(base + 4096 + ao));
            }
        }
        int br = (lane & 7) + ((lane >> 4) & 1) * 8;
        uint32_t bkh = (lane >> 3) & 1;
#pragma unroll
        for (int g16 = 0; g16 < 2; g16++) {
            uint32_t bo = swz((uint32_t)(warp_n * 32 + g16 * 16 + br), bkh);
            uint32_t bgh[4], bgl[4], buh[4], bul[4];
            ldsm_x4(bgh, smem_u32(base + 8192 + 0 * 2048 + bo));
            ldsm_x4(bgl, smem_u32(base + 8192 + 1 * 2048 + bo));
            ldsm_x4(buh, smem_u32(base + 8192 + 2 * 2048 + bo));
            ldsm_x4(bul, smem_u32(base + 8192 + 3 * 2048 + bo));
#pragma unroll
            for (int hh = 0; hh < 2; hh++) {
                int nt = g16 * 2 + hh;
#pragma unroll
                for (int mt = 0; mt < 2; mt++) {
                    mma_bf16(accg[mt][nt], ah[mt], bgh + 2 * hh);
                    mma_bf16(accg[mt][nt], ah[mt], bgl + 2 * hh);
                    mma_bf16(accg[mt][nt], al[mt], bgh + 2 * hh);
                    mma_bf16(accu[mt][nt], ah[mt], buh + 2 * hh);
                    mma_bf16(accu[mt][nt], ah[mt], bul + 2 * hh);
                    mma_bf16(accu[mt][nt], al[mt], buh + 2 * hh);
                }
            }
        }
        cs = cs + 1; if (cs == 3) cs = 0;
    }

    // epilogue: SwiGLU + split-store activations
    int gq = lane >> 2, tq = lane & 3;
#pragma unroll
    for (int mt = 0; mt < 2; mt++)
#pragma unroll
        for (int nt = 0; nt < 4; nt++) {
            int fc = f0 + warp_n * 32 + nt * 8 + tq * 2;
#pragma unroll
            for (int h2 = 0; h2 < 2; h2++) {
                int row = rowbase + warp_m * 32 + mt * 16 + gq + h2 * 8;
                if (row < n) {
                    float g0 = accg[mt][nt][h2 * 2],     g1 = accg[mt][nt][h2 * 2 + 1];
                    float u0 = accu[mt][nt][h2 * 2],     u1 = accu[mt][nt][h2 * 2 + 1];
                    float v0 = g0 / (1.f + expf(-g0)) * u0;
                    float v1 = g1 / (1.f + expf(-g1)) * u1;
                    uint32_t hh, ll;
                    split2(v0, v1, hh, ll);
                    size_t basei = (size_t)(off + row) * F_DIM + fc;
                    *(uint32_t*)(g_acth + basei) = hh;
                    *(uint32_t*)(g_actl + basei) = ll;
                }
            }
        }
}

// ---------------- launch 5: down GEMM -----------------------------------------
// BM=128, BN=128, BK=16, 256 thr, warps 4x2 (32x64 tiles), 3-stage, 2 CTA/SM
__global__ void __launch_bounds__(256, 2)
down_kernel() {
    extern __shared__ char smem[];
    int e = blockIdx.z;
    int n = g_count[e];
    int rowbase = blockIdx.y * 128;
    if (rowbase >= n) return;
    int off = g_offset[e];
    int h0  = blockIdx.x * 128;

    int tid = threadIdx.x, lane = tid & 31, wid = tid >> 5;
    int warp_m = wid >> 1, warp_n = wid & 1;

    int arow = tid >> 1, ahalf = tid & 1;
    int srow = rowbase + arow; if (srow > n - 1) srow = n - 1;
    size_t aoff = (size_t)(off + srow) * F_DIM + ahalf * 8;
    const uint16_t* asrc_h = g_acth + aoff;
    const uint16_t* asrc_l = g_actl + aoff;
    uint32_t adst = swz(arow, ahalf);

    // B loader: 2 mats x 128 rows x 2 halves = 512 -> 2 cpa16/thread
    const uint16_t* bsrc[2];
    uint32_t bdst[2];
#pragma unroll
    for (int c = 0; c < 2; c++) {
        int idx = tid + c * 256;
        int mat = idx >> 8, rem = idx & 255;
        int brow = rem >> 1, bh = rem & 1;
        const uint16_t* base = mat ? g_bdl : g_bdh;
        bsrc[c] = base + (size_t)e * H_DIM * F_DIM + (size_t)(h0 + brow) * F_DIM + bh * 8;
        bdst[c] = 8192 + mat * 4096 + swz(brow, bh);
    }

    float acc[2][8][4];
#pragma unroll
    for (int i = 0; i < 2; i++)
#pragma unroll
        for (int j = 0; j < 8; j++)
#pragma unroll
            for (int q = 0; q < 4; q++) acc[i][j][q] = 0.f;

    auto load_tile = [&](int st, int kt) {
        char* base = smem + st * DN_STAGE;
        cpa16(base + adst,        asrc_h + kt * 16);
        cpa16(base + 4096 + adst, asrc_l + kt * 16);
        cpa16(base + bdst[0], bsrc[0] + kt * 16);
        cpa16(base + bdst[1], bsrc[1] + kt * 16);
        cp_commit();
    };

    load_tile(0, 0);
    load_tile(1, 1);
    const int KT = F_DIM / 16;   // 256
    int cs = 0;
#pragma unroll 1
    for (int kt = 0; kt < KT; kt++) {
        if (kt + 1 < KT) cp_wait1(); else cp_wait0();
        __syncthreads();
        if (kt + 2 < KT) {
            int ld = cs + 2; if (ld >= 3) ld -= 3;
            load_tile(ld, kt + 2);
        }

        char* base = smem + cs * DN_STAGE;
        uint32_t ah[2][4], al[2][4];
        {
            int r8 = (lane & 7) + ((lane >> 3) & 1) * 8;
            uint32_t kh = (lane >> 4) & 1;
#pragma unroll
            for (int mt = 0; mt < 2; mt++) {
                uint32_t ao = swz((uint32_t)(warp_m * 32 + mt * 16 + r8), kh);
                ldsm_x4(ah[mt], smem_u32(base + ao));
                ldsm_x4(al[mt], smem_u32(base + 4096 + ao));
            }
        }
        int br = (lane & 7) + ((lane >> 4) & 1) * 8;
        uint32_t bkh = (lane >> 3) & 1;
#pragma unroll
        for (int g16 = 0; g16 < 4; g16++) {
            uint32_t bo = swz((uint32_t)(warp_n * 64 + g16 * 16 + br), bkh);
            uint32_t bh[4], bl[4];
            ldsm_x4(bh, smem_u32(base + 8192 + bo));
            ldsm_x4(bl, smem_u32(base + 8192 + 4096 + bo));
#pragma unroll
            for (int hh = 0; hh < 2; hh++) {
                int nt = g16 * 2 + hh;
#pragma unroll
                for (int mt = 0; mt < 2; mt++) {
                    mma_bf16(acc[mt][nt], ah[mt], bh + 2 * hh);
                    mma_bf16(acc[mt][nt], ah[mt], bl + 2 * hh);
                    mma_bf16(acc[mt][nt], al[mt], bh + 2 * hh);
                }
            }
        }
        cs = cs + 1; if (cs == 3) cs = 0;
    }

    int gq = lane >> 2, tq = lane & 3;
#pragma unroll
    for (int mt = 0; mt < 2; mt++)
#pragma unroll
        for (int nt = 0; nt < 8; nt++) {
            int hc = h0 + warp_n * 64 + nt * 8 + tq * 2;
#pragma unroll
            for (int h2 = 0; h2 < 2; h2++) {
                int row = rowbase + warp_m * 32 + mt * 16 + gq + h2 * 8;
                if (row < n) {
                    float2 v = make_float2(acc[mt][nt][h2 * 2], acc[mt][nt][h2 * 2 + 1]);
                    *(float2*)(g_part + (size_t)(off + row) * H_DIM + hc) = v;
                }
            }
        }
}

// ---------------- launch 6: combine -------------------------------------------
__global__ void combine_kernel(float* __restrict__ out) {
    int idx = blockIdx.x * blockDim.x + threadIdx.x;
    if (idx >= T_TOK * H_DIM) return;
    int t = idx >> 10;
    int h = idx & 1023;
    int   s0 = g_slot_of[t * 2 + 0];
    int   s1 = g_slot_of[t * 2 + 1];
    float w0 = g_tok_w[t * 2 + 0];
    float w1 = g_tok_w[t * 2 + 1];
    out[idx] = w0 * g_part[(size_t)s0 * H_DIM + h] +
               w1 * g_part[(size_t)s1 * H_DIM + h];
}

// ---------------- launch -----------------------------------------------------
extern "C" void kernel_launch(void* const* d_in, const int* in_sizes, int n_in,
                              void* d_out, int out_size) {
    const float* x      = (const float*)d_in[0];
    const float* gate_w = (const float*)d_in[1];
    const float* w_gate = (const float*)d_in[2];
    const float* w_up   = (const float*)d_in[3];
    const float* w_down = (const float*)d_in[4];
    float* out = (float*)d_out;

    cudaFuncSetAttribute(gateup_kernel, cudaFuncAttributeMaxDynamicSharedMemorySize, GU_SMEM);
    cudaFuncSetAttribute(down_kernel,   cudaFuncAttributeMaxDynamicSharedMemorySize, DN_SMEM);

    split_transpose_zero<<<3 * 8 * 32 * 128, 256>>>(w_gate, w_up, w_down);  // 1
    router_splitx<<<T_TOK / 8, 256>>>(x, gate_w);                           // 2
    scan_scatter_kernel<<<1, 256>>>();                                      // 3
    gateup_kernel<<<dim3(F_DIM / 64, NSLOT / 128, N_EXP), 256, GU_SMEM>>>();// 4 (profiled)
    down_kernel<<<dim3(H_DIM / 128, NSLOT / 128, N_EXP), 256, DN_SMEM>>>(); // 5
    combine_kernel<<<(T_TOK * H_DIM) / 256, 256>>>(out);                    // 6
}